// round 3
// baseline (speedup 1.0000x reference)
#include <cuda_runtime.h>

// Problem constants
#define CB 2
#define CS 2048
#define CD 1024
#define CH 16
#define CHD 64
#define CM (CB*CS)          // 4096 rows total

// Scratch (allocation-free rule: __device__ globals)
__device__ float g_q[CB*CH*CS*CHD];     // [B,H,S,hd]
__device__ float g_k[CB*CH*CS*CHD];
__device__ float g_v[CB*CH*CS*CHD];
__device__ float g_attn[CB*CS*CD];      // [B,S,D] pre-out-proj

// ---------------------------------------------------------------------------
// SGEMM core: y[m,n] = sum_k A[m,k] * W[n,k]   (both K-major), K = 1024
// 128x128 tile, BK=8, 256 threads, 8x8 per-thread microtile. Static smem only.
// ---------------------------------------------------------------------------

__global__ __launch_bounds__(256) void qkv_gemm_kernel(
    const float* __restrict__ x, const float* __restrict__ w)
{
    __shared__ float As[8][132];   // [k][m], pitch 132 (16B aligned rows)
    __shared__ float Bs[8][132];   // [k][n]

    const int tid = threadIdx.x;
    const int m0 = blockIdx.y * 128;
    const int n0 = blockIdx.x * 128;
    const int lr = tid >> 1;           // 0..127
    const int lk = (tid & 1) * 4;      // 0 or 4
    const int ty = tid >> 4;           // 0..15 -> 8 rows
    const int tx = tid & 15;           // 0..15 -> 8 cols

    const float* xp = x + (size_t)(m0 + lr) * CD + lk;
    const float* wp = w + (size_t)(n0 + lr) * CD + lk;

    float acc[8][8];
    #pragma unroll
    for (int i = 0; i < 8; i++)
        #pragma unroll
        for (int j = 0; j < 8; j++) acc[i][j] = 0.0f;

    for (int k0 = 0; k0 < CD; k0 += 8) {
        float4 av = *(const float4*)(xp + k0);
        float4 bv = *(const float4*)(wp + k0);
        __syncthreads();
        As[lk+0][lr] = av.x; As[lk+1][lr] = av.y; As[lk+2][lr] = av.z; As[lk+3][lr] = av.w;
        Bs[lk+0][lr] = bv.x; Bs[lk+1][lr] = bv.y; Bs[lk+2][lr] = bv.z; Bs[lk+3][lr] = bv.w;
        __syncthreads();

        #pragma unroll
        for (int kk = 0; kk < 8; kk++) {
            float a[8], b[8];
            *(float4*)(a)   = *(const float4*)&As[kk][ty*8];
            *(float4*)(a+4) = *(const float4*)&As[kk][ty*8+4];
            *(float4*)(b)   = *(const float4*)&Bs[kk][tx*8];
            *(float4*)(b+4) = *(const float4*)&Bs[kk][tx*8+4];
            #pragma unroll
            for (int i = 0; i < 8; i++)
                #pragma unroll
                for (int j = 0; j < 8; j++)
                    acc[i][j] += a[i] * b[j];
        }
    }

    // Scatter epilogue: column n -> head h = n/192, j = n%192:
    //   j<64 -> Q[d=j], j<128 -> K[d=j-64], else V[d=j-128], layout [B,H,S,hd]
    #pragma unroll
    for (int j = 0; j < 8; j++) {
        int n = n0 + tx*8 + j;
        int hh = n / 192;
        int r  = n - hh * 192;
        float* buf = (r < 64) ? g_q : (r < 128 ? g_k : g_v);
        int dd = r & 63;
        float* base = buf + (size_t)hh * (CS*CHD) + dd;
        #pragma unroll
        for (int i = 0; i < 8; i++) {
            int m  = m0 + ty*8 + i;
            int bb = m >> 11;        // /2048
            int ss = m & 2047;
            base[(size_t)bb * (CH*CS*CHD) + (size_t)ss * CHD] = acc[i][j];
        }
    }
}

__global__ __launch_bounds__(256) void out_gemm_kernel(
    const float* __restrict__ w, const float* __restrict__ bias,
    float* __restrict__ y)
{
    __shared__ float As[8][132];
    __shared__ float Bs[8][132];

    const int tid = threadIdx.x;
    const int m0 = blockIdx.y * 128;
    const int n0 = blockIdx.x * 128;
    const int lr = tid >> 1;
    const int lk = (tid & 1) * 4;
    const int ty = tid >> 4;
    const int tx = tid & 15;

    const float* xp = g_attn + (size_t)(m0 + lr) * CD + lk;
    const float* wp = w      + (size_t)(n0 + lr) * CD + lk;

    float acc[8][8];
    #pragma unroll
    for (int i = 0; i < 8; i++)
        #pragma unroll
        for (int j = 0; j < 8; j++) acc[i][j] = 0.0f;

    for (int k0 = 0; k0 < CD; k0 += 8) {
        float4 av = *(const float4*)(xp + k0);
        float4 bv = *(const float4*)(wp + k0);
        __syncthreads();
        As[lk+0][lr] = av.x; As[lk+1][lr] = av.y; As[lk+2][lr] = av.z; As[lk+3][lr] = av.w;
        Bs[lk+0][lr] = bv.x; Bs[lk+1][lr] = bv.y; Bs[lk+2][lr] = bv.z; Bs[lk+3][lr] = bv.w;
        __syncthreads();

        #pragma unroll
        for (int kk = 0; kk < 8; kk++) {
            float a[8], b[8];
            *(float4*)(a)   = *(const float4*)&As[kk][ty*8];
            *(float4*)(a+4) = *(const float4*)&As[kk][ty*8+4];
            *(float4*)(b)   = *(const float4*)&Bs[kk][tx*8];
            *(float4*)(b+4) = *(const float4*)&Bs[kk][tx*8+4];
            #pragma unroll
            for (int i = 0; i < 8; i++)
                #pragma unroll
                for (int j = 0; j < 8; j++)
                    acc[i][j] += a[i] * b[j];
        }
    }

    float bj[8];
    #pragma unroll
    for (int j = 0; j < 8; j++) bj[j] = bias[n0 + tx*8 + j];

    #pragma unroll
    for (int i = 0; i < 8; i++) {
        float* yp = y + (size_t)(m0 + ty*8 + i) * CD + n0 + tx*8;
        float4 v0, v1;
        v0.x = acc[i][0] + bj[0]; v0.y = acc[i][1] + bj[1];
        v0.z = acc[i][2] + bj[2]; v0.w = acc[i][3] + bj[3];
        v1.x = acc[i][4] + bj[4]; v1.y = acc[i][5] + bj[5];
        v1.z = acc[i][6] + bj[6]; v1.w = acc[i][7] + bj[7];
        *(float4*)(yp)     = v0;
        *(float4*)(yp + 4) = v1;
    }
}

// ---------------------------------------------------------------------------
// Flash attention: grid (S/64, H, B), 256 threads, 48KB STATIC smem.
//   Qs/Ks: transposed [d][slot] tiles with float4-granular XOR swizzle
//          (slot ^= d&15): conflict-free float4 reads, ~4-way store conflicts.
//   Vs:    row-major [kv][d], conflict-free both directions.
//   P matrix lives in registers; P*V sources P via __shfl_sync (each row's
//   64 P values reside within one warp: src lane = (lane&16) + (j>>2)).
// ---------------------------------------------------------------------------

__device__ __forceinline__ float rmax16(float v) {
    v = fmaxf(v, __shfl_xor_sync(0xffffffffu, v, 8, 16));
    v = fmaxf(v, __shfl_xor_sync(0xffffffffu, v, 4, 16));
    v = fmaxf(v, __shfl_xor_sync(0xffffffffu, v, 2, 16));
    v = fmaxf(v, __shfl_xor_sync(0xffffffffu, v, 1, 16));
    return v;
}
__device__ __forceinline__ float rsum16(float v) {
    v += __shfl_xor_sync(0xffffffffu, v, 8, 16);
    v += __shfl_xor_sync(0xffffffffu, v, 4, 16);
    v += __shfl_xor_sync(0xffffffffu, v, 2, 16);
    v += __shfl_xor_sync(0xffffffffu, v, 1, 16);
    return v;
}

__global__ __launch_bounds__(256) void attn_kernel()
{
    __shared__ float Qs[64*64];   // Qt[d][q swizzled], pre-scaled by 1/8
    __shared__ float Ks[64*64];   // Kt[d][kv swizzled]
    __shared__ float Vs[64*64];   // V [kv][d]

    const int tid  = threadIdx.x;
    const int ty   = tid >> 4;          // 0..15 -> 4 query rows each
    const int tx   = tid & 15;          // 0..15 -> 4 kv cols each
    const int lane = tid & 31;
    const int half = lane & 16;         // 0 or 16: which half-warp holds my rows

    const int q0 = blockIdx.x * 64;
    const int h  = blockIdx.y;
    const int b  = blockIdx.z;

    const float* Qg = g_q + ((size_t)(b*CH + h) * CS + q0) * CHD;
    const float* Kg = g_k + (size_t)(b*CH + h) * CS * CHD;
    const float* Vg = g_v + (size_t)(b*CH + h) * CS * CHD;

    // Load Q tile transposed+swizzled, folding in 1/sqrt(hd) = 1/8
    for (int i = tid; i < 64*64; i += 256) {
        int r = i >> 6, d = i & 63;
        Qs[d*64 + ((((r>>2) ^ (d & 15)) << 2) | (r & 3))] = Qg[i] * 0.125f;
    }

    float mrun[4], lrun[4], O[4][4];
    #pragma unroll
    for (int i = 0; i < 4; i++) {
        mrun[i] = -1e30f; lrun[i] = 0.0f;
        #pragma unroll
        for (int c = 0; c < 4; c++) O[i][c] = 0.0f;
    }

    for (int kt = 0; kt < CS/64; kt++) {
        __syncthreads();  // prior S-compute / PV reads of Ks/Vs (and Q store) done
        const float* Kt = Kg + (size_t)kt * 64 * CHD;
        const float* Vt = Vg + (size_t)kt * 64 * CHD;
        for (int i = tid; i < 64*64; i += 256) {
            int r = i >> 6, d = i & 63;
            Ks[d*64 + ((((r>>2) ^ (d & 15)) << 2) | (r & 3))] = Kt[i];
            Vs[i] = Vt[i];   // i = r*64 + d, row-major
        }
        __syncthreads();

        // S = (Q/8) K^T : each thread 4 q-rows x 4 kv-cols
        float s[4][4];
        #pragma unroll
        for (int i = 0; i < 4; i++)
            #pragma unroll
            for (int j = 0; j < 4; j++) s[i][j] = 0.0f;

        #pragma unroll 16
        for (int d = 0; d < 64; d++) {
            const int sw = (d & 15);
            float4 q = *(const float4*)&Qs[d*64 + ((ty ^ sw) << 2)];
            float4 k = *(const float4*)&Ks[d*64 + ((tx ^ sw) << 2)];
            s[0][0] += q.x*k.x; s[0][1] += q.x*k.y; s[0][2] += q.x*k.z; s[0][3] += q.x*k.w;
            s[1][0] += q.y*k.x; s[1][1] += q.y*k.y; s[1][2] += q.y*k.z; s[1][3] += q.y*k.w;
            s[2][0] += q.z*k.x; s[2][1] += q.z*k.y; s[2][2] += q.z*k.z; s[2][3] += q.z*k.w;
            s[3][0] += q.w*k.x; s[3][1] += q.w*k.y; s[3][2] += q.w*k.z; s[3][3] += q.w*k.w;
        }

        // Online softmax per row (row shared by 16 tx-threads); p stays in regs
        #pragma unroll
        for (int i = 0; i < 4; i++) {
            float mx = fmaxf(fmaxf(s[i][0], s[i][1]), fmaxf(s[i][2], s[i][3]));
            mx = rmax16(mx);
            float mnew = fmaxf(mrun[i], mx);
            float sc = __expf(mrun[i] - mnew);   // first tile: exp(-inf)=0, no NaN
            s[i][0] = __expf(s[i][0] - mnew);
            s[i][1] = __expf(s[i][1] - mnew);
            s[i][2] = __expf(s[i][2] - mnew);
            s[i][3] = __expf(s[i][3] - mnew);
            float ls = rsum16(s[i][0] + s[i][1] + s[i][2] + s[i][3]);
            lrun[i] = lrun[i] * sc + ls;
            mrun[i] = mnew;
            #pragma unroll
            for (int c = 0; c < 4; c++) O[i][c] *= sc;
        }

        // O += P @ V, P sourced via shuffle: P[myrow i][j] lives in lane
        // (half + (j>>2)), register s[i][j&3].
        #pragma unroll
        for (int j4 = 0; j4 < 16; j4++) {
            const int src = half + j4;
            #pragma unroll
            for (int c = 0; c < 4; c++) {
                const int j = j4*4 + c;
                float4 v = *(const float4*)&Vs[j*64 + (tx << 2)];
                float p0 = __shfl_sync(0xffffffffu, s[0][c], src);
                float p1 = __shfl_sync(0xffffffffu, s[1][c], src);
                float p2 = __shfl_sync(0xffffffffu, s[2][c], src);
                float p3 = __shfl_sync(0xffffffffu, s[3][c], src);
                O[0][0] += p0*v.x; O[0][1] += p0*v.y; O[0][2] += p0*v.z; O[0][3] += p0*v.w;
                O[1][0] += p1*v.x; O[1][1] += p1*v.y; O[1][2] += p1*v.z; O[1][3] += p1*v.w;
                O[2][0] += p2*v.x; O[2][1] += p2*v.y; O[2][2] += p2*v.z; O[2][3] += p2*v.w;
                O[3][0] += p3*v.x; O[3][1] += p3*v.y; O[3][2] += p3*v.z; O[3][3] += p3*v.w;
            }
        }
    }

    // Normalize and write to [B,S,D] (head-interleaved)
    #pragma unroll
    for (int i = 0; i < 4; i++) {
        int q = q0 + ty*4 + i;
        float inv = 1.0f / lrun[i];
        float4 o;
        o.x = O[i][0]*inv; o.y = O[i][1]*inv; o.z = O[i][2]*inv; o.w = O[i][3]*inv;
        *(float4*)&g_attn[((size_t)b*CS + q)*CD + h*CHD + (tx<<2)] = o;
    }
}

// ---------------------------------------------------------------------------

extern "C" void kernel_launch(void* const* d_in, const int* in_sizes, int n_in,
                              void* d_out, int out_size)
{
    const float* latents = (const float*)d_in[0];   // [2,2048,1024]
    const float* w_qkv   = (const float*)d_in[1];   // [3072,1024]
    const float* w_out   = (const float*)d_in[2];   // [1024,1024]
    const float* b_out   = (const float*)d_in[3];   // [1024]
    float* out = (float*)d_out;

    (void)in_sizes; (void)n_in; (void)out_size;

    // 1) QKV projection: [4096,1024] x [3072,1024]^T, scatter to Q/K/V
    qkv_gemm_kernel<<<dim3(3072/128, CM/128), 256>>>(latents, w_qkv);

    // 2) Flash attention per (b,h,q-tile) — static 48KB smem, no attributes
    attn_kernel<<<dim3(CS/64, CH, CB), 256>>>();

    // 3) Output projection + bias
    out_gemm_kernel<<<dim3(CD/128, CM/128), 256>>>(w_out, b_out, out);
}

// round 6
// speedup vs baseline: 1.3894x; 1.3894x over previous
#include <cuda_runtime.h>
#include <cuda_bf16.h>
#include <cstdint>

// Problem constants
#define CB 2
#define CS 2048
#define CD 1024
#define CH 16
#define CHD 64
#define CM 4096          // B*S rows
#define NQKV 3072
#define CHUNK 16
#define NCHUNK (CD/CHUNK)   // 64

// ---------------------------------------------------------------------------
// Device-global scratch (allocation-free rule)
// ---------------------------------------------------------------------------
__device__ __nv_bfloat16 g_xh[(size_t)CM*CD],  g_xl[(size_t)CM*CD];      // latents hi/lo
__device__ __nv_bfloat16 g_wqh[(size_t)NQKV*CD], g_wql[(size_t)NQKV*CD]; // w_qkv hi/lo
__device__ __nv_bfloat16 g_woh[(size_t)CD*CD], g_wol[(size_t)CD*CD];     // w_out hi/lo
__device__ __nv_bfloat16 g_ah[(size_t)CM*CD],  g_al[(size_t)CM*CD];      // attn out hi/lo
__device__ float g_qkv[(size_t)CM*NQKV];   // row-major [4096, 3072]
__device__ float g_attn[(size_t)CM*CD];    // [B,S,D] pre-out-proj

// ---------------------------------------------------------------------------
// PTX helpers (arch-agnostic: ldmatrix + mma.sync, sm_80+)
// ---------------------------------------------------------------------------
static __device__ __forceinline__ uint32_t s2u(const void* p){
    uint32_t a;
    asm("{ .reg .u64 t; cvta.to.shared.u64 t, %1; cvt.u32.u64 %0, t; }" : "=r"(a) : "l"(p));
    return a;
}
#define LDSM4(r, addr) \
    asm volatile("ldmatrix.sync.aligned.m8n8.x4.shared.b16 {%0,%1,%2,%3}, [%4];" \
        : "=r"((r)[0]), "=r"((r)[1]), "=r"((r)[2]), "=r"((r)[3]) : "r"(addr))
#define LDSM2(r, addr) \
    asm volatile("ldmatrix.sync.aligned.m8n8.x2.shared.b16 {%0,%1}, [%2];" \
        : "=r"((r)[0]), "=r"((r)[1]) : "r"(addr))
#define MMA16816(d, a, b) \
    asm volatile("mma.sync.aligned.m16n8k16.row.col.f32.bf16.bf16.f32 " \
        "{%0,%1,%2,%3}, {%4,%5,%6,%7}, {%8,%9}, {%0,%1,%2,%3};" \
        : "+f"((d)[0]), "+f"((d)[1]), "+f"((d)[2]), "+f"((d)[3]) \
        : "r"((a)[0]), "r"((a)[1]), "r"((a)[2]), "r"((a)[3]), "r"((b)[0]), "r"((b)[1]))
#define CPASYNC16(dst, src) \
    asm volatile("cp.async.cg.shared.global [%0], [%1], 16;" :: "r"(dst), "l"(src) : "memory")

// ---------------------------------------------------------------------------
// fp32 -> bf16 hi/lo split conversion
// ---------------------------------------------------------------------------
static __device__ __forceinline__ void conv_body(const float4* __restrict__ src,
    __nv_bfloat16* __restrict__ hi, __nv_bfloat16* __restrict__ lo, int n4)
{
    int i = blockIdx.x * 256 + threadIdx.x;
    if (i >= n4) return;
    float4 v = src[i];
    __nv_bfloat162 h01 = __floats2bfloat162_rn(v.x, v.y);
    __nv_bfloat162 h23 = __floats2bfloat162_rn(v.z, v.w);
    __nv_bfloat162 l01 = __floats2bfloat162_rn(v.x - __low2float(h01), v.y - __high2float(h01));
    __nv_bfloat162 l23 = __floats2bfloat162_rn(v.z - __low2float(h23), v.w - __high2float(h23));
    uint2 H, L;
    H.x = *reinterpret_cast<unsigned*>(&h01); H.y = *reinterpret_cast<unsigned*>(&h23);
    L.x = *reinterpret_cast<unsigned*>(&l01); L.y = *reinterpret_cast<unsigned*>(&l23);
    *reinterpret_cast<uint2*>(hi + (size_t)i*4) = H;
    *reinterpret_cast<uint2*>(lo + (size_t)i*4) = L;
}
__global__ __launch_bounds__(256) void conv_x (const float4* s){ conv_body(s, g_xh,  g_xl,  CM*CD/4); }
__global__ __launch_bounds__(256) void conv_wq(const float4* s){ conv_body(s, g_wqh, g_wql, NQKV*CD/4); }
__global__ __launch_bounds__(256) void conv_wo(const float4* s){ conv_body(s, g_woh, g_wol, CD*CD/4); }
__global__ __launch_bounds__(256) void conv_a (void){ conv_body((const float4*)g_attn, g_ah, g_al, CM*CD/4); }

// ---------------------------------------------------------------------------
// mma.sync bf16-split GEMM: out[m,n] = sum_k A[m,k]*B[n,k], K=1024.
// CTA 128x128, K-chunk 16, 2-stage cp.async pipeline, static 32KB smem.
// Tile layout in smem: [128 rows][16 bf16 = 32B], 16B halves XOR-swizzled by
// (row>>2)&1 -> conflict-free ldmatrix (8 rows x 16B spread over 128B line).
// which==0: A=g_xh/l, B=g_wqh/l, out=g_qkv (ld 3072), no bias
// which==1: A=g_ah/l, B=g_woh/l, out=param  (ld 1024), + bias
// ---------------------------------------------------------------------------
__global__ __launch_bounds__(256, 2) void mm_bf16(int which, float* __restrict__ outp,
                                                  const float* __restrict__ bias)
{
    __shared__ __align__(1024) uint8_t sm[2][4][4096];   // [stage][Ah,Al,Bh,Bl][128x32B]

    const int tid  = threadIdx.x;
    const int m0   = blockIdx.y * 128;
    const int n0   = blockIdx.x * 128;

    const __nv_bfloat16 *Ah, *Al, *Bh, *Bl;
    float* out; int nld;
    if (which == 0) { Ah=g_xh; Al=g_xl; Bh=g_wqh; Bl=g_wql; out=g_qkv; nld=NQKV; }
    else            { Ah=g_ah; Al=g_al; Bh=g_woh; Bl=g_wol; out=outp;  nld=CD;   }

    // ---- loader setup: thread t -> row=t>>1 (0..127), kc=t&1 (16B half) ----
    const int lrow = tid >> 1;
    const int lkc  = tid & 1;
    const uint32_t smbase = s2u(&sm[0][0][0]);
    const uint32_t dsto   = lrow*32 + ((lkc ^ ((lrow>>2)&1)) << 4);
    const __nv_bfloat16* srcp[4] = {
        Ah + (size_t)(m0+lrow)*CD + lkc*8,
        Al + (size_t)(m0+lrow)*CD + lkc*8,
        Bh + (size_t)(n0+lrow)*CD + lkc*8,
        Bl + (size_t)(n0+lrow)*CD + lkc*8 };

    // ---- compute setup: warp w -> 64x32 subtile ----
    const int warp = tid >> 5, lane = tid & 31;
    const int wm = (warp >> 2) * 64;
    const int wn = (warp & 3) * 32;
    uint32_t offA[4], offB[4];
    #pragma unroll
    for (int mt = 0; mt < 4; mt++) {
        int r  = wm + mt*16 + (lane & 15);
        int kc = lane >> 4;
        offA[mt] = r*32 + ((kc ^ ((r>>2)&1)) << 4);
    }
    #pragma unroll
    for (int nt = 0; nt < 4; nt++) {
        int il = lane & 15;
        int r  = wn + nt*8 + (il & 7);
        int kc = (il >> 3) & 1;
        offB[nt] = r*32 + ((kc ^ ((r>>2)&1)) << 4);
    }

    float acc[4][4][4];
    #pragma unroll
    for (int mt = 0; mt < 4; mt++)
        #pragma unroll
        for (int nt = 0; nt < 4; nt++)
            #pragma unroll
            for (int e = 0; e < 4; e++) acc[mt][nt][e] = 0.0f;

    // ---- prologue: stage 0 loads chunk 0 ----
    #pragma unroll
    for (int t = 0; t < 4; t++)
        CPASYNC16(smbase + t*4096 + dsto, srcp[t]);
    asm volatile("cp.async.commit_group;" ::: "memory");

    for (int c = 0; c < NCHUNK; c++) {
        if (c + 1 < NCHUNK) {
            const uint32_t db = smbase + ((c+1)&1)*16384;
            #pragma unroll
            for (int t = 0; t < 4; t++)
                CPASYNC16(db + t*4096 + dsto, srcp[t] + (c+1)*CHUNK);
            asm volatile("cp.async.commit_group;" ::: "memory");
            asm volatile("cp.async.wait_group 1;" ::: "memory");
        } else {
            asm volatile("cp.async.wait_group 0;" ::: "memory");
        }
        __syncthreads();

        const uint32_t sb  = smbase + (c&1)*16384;
        const uint32_t aAh = sb, aAl = sb + 4096, aBh = sb + 8192, aBl = sb + 12288;

        uint32_t af[4][4], bh[4][2], bl[4][2];
        #pragma unroll
        for (int mt = 0; mt < 4; mt++) LDSM4(af[mt], aAh + offA[mt]);
        #pragma unroll
        for (int nt = 0; nt < 4; nt++) LDSM2(bh[nt], aBh + offB[nt]);
        #pragma unroll
        for (int mt = 0; mt < 4; mt++)
            #pragma unroll
            for (int nt = 0; nt < 4; nt++) MMA16816(acc[mt][nt], af[mt], bh[nt]);

        #pragma unroll
        for (int nt = 0; nt < 4; nt++) LDSM2(bl[nt], aBl + offB[nt]);
        #pragma unroll
        for (int mt = 0; mt < 4; mt++)
            #pragma unroll
            for (int nt = 0; nt < 4; nt++) MMA16816(acc[mt][nt], af[mt], bl[nt]);

        #pragma unroll
        for (int mt = 0; mt < 4; mt++) LDSM4(af[mt], aAl + offA[mt]);   // reuse regs
        #pragma unroll
        for (int mt = 0; mt < 4; mt++)
            #pragma unroll
            for (int nt = 0; nt < 4; nt++) MMA16816(acc[mt][nt], af[mt], bh[nt]);

        __syncthreads();
    }

    // ---- epilogue: C layout m16n8 -> row=group(+8), col=(lane&3)*2+{0,1} ----
    const int group = lane >> 2, lane4 = lane & 3;
    #pragma unroll
    for (int mt = 0; mt < 4; mt++) {
        #pragma unroll
        for (int nt = 0; nt < 4; nt++) {
            int m = m0 + wm + mt*16 + group;
            int n = n0 + wn + nt*8 + lane4*2;
            float b0 = 0.f, b1 = 0.f;
            if (which) { b0 = bias[n]; b1 = bias[n+1]; }
            float2 v0, v1;
            v0.x = acc[mt][nt][0] + b0; v0.y = acc[mt][nt][1] + b1;
            v1.x = acc[mt][nt][2] + b0; v1.y = acc[mt][nt][3] + b1;
            *(float2*)&out[(size_t)m*nld + n]     = v0;
            *(float2*)&out[(size_t)(m+8)*nld + n] = v1;
        }
    }
}

// ---------------------------------------------------------------------------
// Flash attention (fp32 SIMT), reading row-major g_qkv:
// row m=b*S+s, cols h*192 + [0..63]=Q, [64..127]=K, [128..191]=V.
// ---------------------------------------------------------------------------
__device__ __forceinline__ float rmax16(float v) {
    v = fmaxf(v, __shfl_xor_sync(0xffffffffu, v, 8, 16));
    v = fmaxf(v, __shfl_xor_sync(0xffffffffu, v, 4, 16));
    v = fmaxf(v, __shfl_xor_sync(0xffffffffu, v, 2, 16));
    v = fmaxf(v, __shfl_xor_sync(0xffffffffu, v, 1, 16));
    return v;
}
__device__ __forceinline__ float rsum16(float v) {
    v += __shfl_xor_sync(0xffffffffu, v, 8, 16);
    v += __shfl_xor_sync(0xffffffffu, v, 4, 16);
    v += __shfl_xor_sync(0xffffffffu, v, 2, 16);
    v += __shfl_xor_sync(0xffffffffu, v, 1, 16);
    return v;
}

__global__ __launch_bounds__(256) void attn_kernel()
{
    __shared__ float Qs[64*64];
    __shared__ float Ks[64*64];
    __shared__ float Vs[64*64];

    const int tid  = threadIdx.x;
    const int ty   = tid >> 4;
    const int tx   = tid & 15;
    const int lane = tid & 31;
    const int half = lane & 16;

    const int q0 = blockIdx.x * 64;
    const int h  = blockIdx.y;
    const int b  = blockIdx.z;

    const float* Qg = g_qkv + (size_t)(b*CS + q0) * NQKV + h*192;
    const float* Kg = g_qkv + (size_t)(b*CS) * NQKV + h*192 + 64;
    const float* Vg = g_qkv + (size_t)(b*CS) * NQKV + h*192 + 128;

    for (int i = tid; i < 64*64; i += 256) {
        int r = i >> 6, d = i & 63;
        Qs[d*64 + ((((r>>2) ^ (d & 15)) << 2) | (r & 3))] = Qg[(size_t)r*NQKV + d] * 0.125f;
    }

    float mrun[4], lrun[4], O[4][4];
    #pragma unroll
    for (int i = 0; i < 4; i++) {
        mrun[i] = -1e30f; lrun[i] = 0.0f;
        #pragma unroll
        for (int c = 0; c < 4; c++) O[i][c] = 0.0f;
    }

    for (int kt = 0; kt < CS/64; kt++) {
        __syncthreads();
        const float* Kt = Kg + (size_t)kt * 64 * NQKV;
        const float* Vt = Vg + (size_t)kt * 64 * NQKV;
        for (int i = tid; i < 64*64; i += 256) {
            int r = i >> 6, d = i & 63;
            Ks[d*64 + ((((r>>2) ^ (d & 15)) << 2) | (r & 3))] = Kt[(size_t)r*NQKV + d];
            Vs[i] = Vt[(size_t)r*NQKV + d];
        }
        __syncthreads();

        float s[4][4];
        #pragma unroll
        for (int i = 0; i < 4; i++)
            #pragma unroll
            for (int j = 0; j < 4; j++) s[i][j] = 0.0f;

        #pragma unroll 16
        for (int d = 0; d < 64; d++) {
            const int sw = (d & 15);
            float4 q = *(const float4*)&Qs[d*64 + ((ty ^ sw) << 2)];
            float4 k = *(const float4*)&Ks[d*64 + ((tx ^ sw) << 2)];
            s[0][0] += q.x*k.x; s[0][1] += q.x*k.y; s[0][2] += q.x*k.z; s[0][3] += q.x*k.w;
            s[1][0] += q.y*k.x; s[1][1] += q.y*k.y; s[1][2] += q.y*k.z; s[1][3] += q.y*k.w;
            s[2][0] += q.z*k.x; s[2][1] += q.z*k.y; s[2][2] += q.z*k.z; s[2][3] += q.z*k.w;
            s[3][0] += q.w*k.x; s[3][1] += q.w*k.y; s[3][2] += q.w*k.z; s[3][3] += q.w*k.w;
        }

        #pragma unroll
        for (int i = 0; i < 4; i++) {
            float mx = fmaxf(fmaxf(s[i][0], s[i][1]), fmaxf(s[i][2], s[i][3]));
            mx = rmax16(mx);
            float mnew = fmaxf(mrun[i], mx);
            float sc = __expf(mrun[i] - mnew);
            s[i][0] = __expf(s[i][0] - mnew);
            s[i][1] = __expf(s[i][1] - mnew);
            s[i][2] = __expf(s[i][2] - mnew);
            s[i][3] = __expf(s[i][3] - mnew);
            float ls = rsum16(s[i][0] + s[i][1] + s[i][2] + s[i][3]);
            lrun[i] = lrun[i] * sc + ls;
            mrun[i] = mnew;
            #pragma unroll
            for (int c = 0; c < 4; c++) O[i][c] *= sc;
        }

        #pragma unroll
        for (int j4 = 0; j4 < 16; j4++) {
            const int src = half + j4;
            #pragma unroll
            for (int c = 0; c < 4; c++) {
                const int j = j4*4 + c;
                float4 v = *(const float4*)&Vs[j*64 + (tx << 2)];
                float p0 = __shfl_sync(0xffffffffu, s[0][c], src);
                float p1 = __shfl_sync(0xffffffffu, s[1][c], src);
                float p2 = __shfl_sync(0xffffffffu, s[2][c], src);
                float p3 = __shfl_sync(0xffffffffu, s[3][c], src);
                O[0][0] += p0*v.x; O[0][1] += p0*v.y; O[0][2] += p0*v.z; O[0][3] += p0*v.w;
                O[1][0] += p1*v.x; O[1][1] += p1*v.y; O[1][2] += p1*v.z; O[1][3] += p1*v.w;
                O[2][0] += p2*v.x; O[2][1] += p2*v.y; O[2][2] += p2*v.z; O[2][3] += p2*v.w;
                O[3][0] += p3*v.x; O[3][1] += p3*v.y; O[3][2] += p3*v.z; O[3][3] += p3*v.w;
            }
        }
    }

    #pragma unroll
    for (int i = 0; i < 4; i++) {
        int q = q0 + ty*4 + i;
        float inv = 1.0f / lrun[i];
        float4 o;
        o.x = O[i][0]*inv; o.y = O[i][1]*inv; o.z = O[i][2]*inv; o.w = O[i][3]*inv;
        *(float4*)&g_attn[((size_t)b*CS + q)*CD + h*CHD + (tx<<2)] = o;
    }
}

// ---------------------------------------------------------------------------

extern "C" void kernel_launch(void* const* d_in, const int* in_sizes, int n_in,
                              void* d_out, int out_size)
{
    const float* latents = (const float*)d_in[0];   // [2,2048,1024]
    const float* w_qkv   = (const float*)d_in[1];   // [3072,1024]
    const float* w_out   = (const float*)d_in[2];   // [1024,1024]
    const float* b_out   = (const float*)d_in[3];   // [1024]
    float* out = (float*)d_out;
    (void)in_sizes; (void)n_in; (void)out_size;

    // hi/lo splits of operands
    conv_x <<<CM*CD/4/256,   256>>>((const float4*)latents);
    conv_wq<<<NQKV*CD/4/256, 256>>>((const float4*)w_qkv);
    conv_wo<<<CD*CD/4/256,   256>>>((const float4*)w_out);

    // QKV projection -> g_qkv [4096, 3072]
    mm_bf16<<<dim3(NQKV/128, CM/128), 256>>>(0, nullptr, nullptr);

    // Flash attention -> g_attn
    attn_kernel<<<dim3(CS/64, CH, CB), 256>>>();

    // out-proj input split, then out GEMM + bias -> d_out
    conv_a<<<CM*CD/4/256, 256>>>();
    mm_bf16<<<dim3(CD/128, CM/128), 256>>>(1, out, b_out);
}

// round 7
// speedup vs baseline: 2.7712x; 1.9946x over previous
#include <cuda_runtime.h>
#include <cuda_bf16.h>
#include <cstdint>

// Problem constants
#define CB 2
#define CS 2048
#define CD 1024
#define CH 16
#define CHD 64
#define CM 4096          // B*S rows
#define NQKV 3072
#define CHUNK 16
#define NCHUNK (CD/CHUNK)   // 64

// ---------------------------------------------------------------------------
// Device-global scratch (allocation-free rule)
// ---------------------------------------------------------------------------
__device__ __nv_bfloat16 g_xh[(size_t)CM*CD],  g_xl[(size_t)CM*CD];      // latents hi/lo
__device__ __nv_bfloat16 g_wqh[(size_t)NQKV*CD], g_wql[(size_t)NQKV*CD]; // w_qkv hi/lo
__device__ __nv_bfloat16 g_woh[(size_t)CD*CD], g_wol[(size_t)CD*CD];     // w_out hi/lo
__device__ __nv_bfloat16 g_ah[(size_t)CM*CD],  g_al[(size_t)CM*CD];      // attn out hi/lo
__device__ float g_qkv[(size_t)CM*NQKV];   // row-major [4096, 3072]
// attention operands (bf16 hi/lo): Q scaled by 0.125*log2e
__device__ __nv_bfloat16 g_qsh[(size_t)CB*CH*CS*CHD], g_qsl[(size_t)CB*CH*CS*CHD]; // [bh,s,d]
__device__ __nv_bfloat16 g_kh2[(size_t)CB*CH*CS*CHD], g_kl2[(size_t)CB*CH*CS*CHD]; // [bh,s,d]
__device__ __nv_bfloat16 g_vth[(size_t)CB*CH*CHD*CS], g_vtl[(size_t)CB*CH*CHD*CS]; // [bh,d,s]

// ---------------------------------------------------------------------------
// PTX helpers (arch-agnostic: ldmatrix + mma.sync, sm_80+)
// ---------------------------------------------------------------------------
static __device__ __forceinline__ uint32_t s2u(const void* p){
    uint32_t a;
    asm("{ .reg .u64 t; cvta.to.shared.u64 t, %1; cvt.u32.u64 %0, t; }" : "=r"(a) : "l"(p));
    return a;
}
static __device__ __forceinline__ float ex2f(float x){
    float r; asm("ex2.approx.f32 %0, %1;" : "=f"(r) : "f"(x)); return r;
}
#define LDSM4(r, addr) \
    asm volatile("ldmatrix.sync.aligned.m8n8.x4.shared.b16 {%0,%1,%2,%3}, [%4];" \
        : "=r"((r)[0]), "=r"((r)[1]), "=r"((r)[2]), "=r"((r)[3]) : "r"(addr))
#define LDSM2(r, addr) \
    asm volatile("ldmatrix.sync.aligned.m8n8.x2.shared.b16 {%0,%1}, [%2];" \
        : "=r"((r)[0]), "=r"((r)[1]) : "r"(addr))
#define MMA16816(d, a, b) \
    asm volatile("mma.sync.aligned.m16n8k16.row.col.f32.bf16.bf16.f32 " \
        "{%0,%1,%2,%3}, {%4,%5,%6,%7}, {%8,%9}, {%0,%1,%2,%3};" \
        : "+f"((d)[0]), "+f"((d)[1]), "+f"((d)[2]), "+f"((d)[3]) \
        : "r"((a)[0]), "r"((a)[1]), "r"((a)[2]), "r"((a)[3]), "r"((b)[0]), "r"((b)[1]))
#define CPASYNC16(dst, src) \
    asm volatile("cp.async.cg.shared.global [%0], [%1], 16;" :: "r"(dst), "l"(src) : "memory")

static __device__ __forceinline__ uint32_t pack_bf2(__nv_bfloat16 a, __nv_bfloat16 b){
    __nv_bfloat162 t = __halves2bfloat162(a, b);   // low = a, high = b
    return *reinterpret_cast<uint32_t*>(&t);
}

// ---------------------------------------------------------------------------
// fp32 -> bf16 hi/lo split conversion (for GEMM operands)
// ---------------------------------------------------------------------------
static __device__ __forceinline__ void conv_body(const float4* __restrict__ src,
    __nv_bfloat16* __restrict__ hi, __nv_bfloat16* __restrict__ lo, int n4)
{
    int i = blockIdx.x * 256 + threadIdx.x;
    if (i >= n4) return;
    float4 v = src[i];
    __nv_bfloat162 h01 = __floats2bfloat162_rn(v.x, v.y);
    __nv_bfloat162 h23 = __floats2bfloat162_rn(v.z, v.w);
    __nv_bfloat162 l01 = __floats2bfloat162_rn(v.x - __low2float(h01), v.y - __high2float(h01));
    __nv_bfloat162 l23 = __floats2bfloat162_rn(v.z - __low2float(h23), v.w - __high2float(h23));
    uint2 H, L;
    H.x = *reinterpret_cast<unsigned*>(&h01); H.y = *reinterpret_cast<unsigned*>(&h23);
    L.x = *reinterpret_cast<unsigned*>(&l01); L.y = *reinterpret_cast<unsigned*>(&l23);
    *reinterpret_cast<uint2*>(hi + (size_t)i*4) = H;
    *reinterpret_cast<uint2*>(lo + (size_t)i*4) = L;
}
__global__ __launch_bounds__(256) void conv_x (const float4* s){ conv_body(s, g_xh,  g_xl,  CM*CD/4); }
__global__ __launch_bounds__(256) void conv_wq(const float4* s){ conv_body(s, g_wqh, g_wql, NQKV*CD/4); }
__global__ __launch_bounds__(256) void conv_wo(const float4* s){ conv_body(s, g_woh, g_wol, CD*CD/4); }

// ---------------------------------------------------------------------------
// Split g_qkv -> attention operands. Grid (CS/64, CH, CB), 256 thr.
// Q scaled by 0.125*log2e (base-2 softmax). V transposed to [bh,d,s] via smem.
// ---------------------------------------------------------------------------
__global__ __launch_bounds__(256) void conv_qkv()
{
    __shared__ float vs[64][65];
    const int tid = threadIdx.x;
    const int kt = blockIdx.x, h = blockIdx.y, b = blockIdx.z;
    const size_t bh = (size_t)b*CH + h;
    const float* base = g_qkv + ((size_t)(b*CS + kt*64))*NQKV + h*192;
    const float QSC = 0.125f * 1.44269504f;

    for (int i = tid; i < 64*16; i += 256) {
        int s = i >> 4, d4 = i & 15;
        const float* p = base + (size_t)s*NQKV + d4*4;
        size_t o = (bh*CS + kt*64 + s)*CHD + d4*4;
        float4 q = *(const float4*)p;
        q.x *= QSC; q.y *= QSC; q.z *= QSC; q.w *= QSC;
        {
            __nv_bfloat162 h01 = __floats2bfloat162_rn(q.x, q.y);
            __nv_bfloat162 h23 = __floats2bfloat162_rn(q.z, q.w);
            __nv_bfloat162 l01 = __floats2bfloat162_rn(q.x - __low2float(h01), q.y - __high2float(h01));
            __nv_bfloat162 l23 = __floats2bfloat162_rn(q.z - __low2float(h23), q.w - __high2float(h23));
            uint2 H = { *(unsigned*)&h01, *(unsigned*)&h23 };
            uint2 L = { *(unsigned*)&l01, *(unsigned*)&l23 };
            *reinterpret_cast<uint2*>(g_qsh + o) = H;
            *reinterpret_cast<uint2*>(g_qsl + o) = L;
        }
        float4 k = *(const float4*)(p + 64);
        {
            __nv_bfloat162 h01 = __floats2bfloat162_rn(k.x, k.y);
            __nv_bfloat162 h23 = __floats2bfloat162_rn(k.z, k.w);
            __nv_bfloat162 l01 = __floats2bfloat162_rn(k.x - __low2float(h01), k.y - __high2float(h01));
            __nv_bfloat162 l23 = __floats2bfloat162_rn(k.z - __low2float(h23), k.w - __high2float(h23));
            uint2 H = { *(unsigned*)&h01, *(unsigned*)&h23 };
            uint2 L = { *(unsigned*)&l01, *(unsigned*)&l23 };
            *reinterpret_cast<uint2*>(g_kh2 + o) = H;
            *reinterpret_cast<uint2*>(g_kl2 + o) = L;
        }
        float4 v = *(const float4*)(p + 128);
        vs[s][d4*4+0] = v.x; vs[s][d4*4+1] = v.y; vs[s][d4*4+2] = v.z; vs[s][d4*4+3] = v.w;
    }
    __syncthreads();
    for (int i = tid; i < 64*16; i += 256) {
        int d = i >> 4, s4 = i & 15;
        float x0 = vs[s4*4+0][d], x1 = vs[s4*4+1][d], x2 = vs[s4*4+2][d], x3 = vs[s4*4+3][d];
        __nv_bfloat16 h0 = __float2bfloat16(x0), h1 = __float2bfloat16(x1);
        __nv_bfloat16 h2 = __float2bfloat16(x2), h3 = __float2bfloat16(x3);
        __nv_bfloat16 l0 = __float2bfloat16(x0 - __bfloat162float(h0));
        __nv_bfloat16 l1 = __float2bfloat16(x1 - __bfloat162float(h1));
        __nv_bfloat16 l2 = __float2bfloat16(x2 - __bfloat162float(h2));
        __nv_bfloat16 l3 = __float2bfloat16(x3 - __bfloat162float(h3));
        size_t o = (bh*CHD + d)*CS + kt*64 + s4*4;
        uint2 H = { pack_bf2(h0,h1), pack_bf2(h2,h3) };
        uint2 L = { pack_bf2(l0,l1), pack_bf2(l2,l3) };
        *reinterpret_cast<uint2*>(g_vth + o) = H;
        *reinterpret_cast<uint2*>(g_vtl + o) = L;
    }
}

// ---------------------------------------------------------------------------
// mma.sync bf16-split GEMM (unchanged from R6, validated): out = A @ B^T
// ---------------------------------------------------------------------------
__global__ __launch_bounds__(256, 2) void mm_bf16(int which, float* __restrict__ outp,
                                                  const float* __restrict__ bias)
{
    __shared__ __align__(1024) uint8_t sm[2][4][4096];

    const int tid  = threadIdx.x;
    const int m0   = blockIdx.y * 128;
    const int n0   = blockIdx.x * 128;

    const __nv_bfloat16 *Ah, *Al, *Bh, *Bl;
    float* out; int nld;
    if (which == 0) { Ah=g_xh; Al=g_xl; Bh=g_wqh; Bl=g_wql; out=g_qkv; nld=NQKV; }
    else            { Ah=g_ah; Al=g_al; Bh=g_woh; Bl=g_wol; out=outp;  nld=CD;   }

    const int lrow = tid >> 1;
    const int lkc  = tid & 1;
    const uint32_t smbase = s2u(&sm[0][0][0]);
    const uint32_t dsto   = lrow*32 + ((lkc ^ ((lrow>>2)&1)) << 4);
    const __nv_bfloat16* srcp[4] = {
        Ah + (size_t)(m0+lrow)*CD + lkc*8,
        Al + (size_t)(m0+lrow)*CD + lkc*8,
        Bh + (size_t)(n0+lrow)*CD + lkc*8,
        Bl + (size_t)(n0+lrow)*CD + lkc*8 };

    const int warp = tid >> 5, lane = tid & 31;
    const int wm = (warp >> 2) * 64;
    const int wn = (warp & 3) * 32;
    uint32_t offA[4], offB[4];
    #pragma unroll
    for (int mt = 0; mt < 4; mt++) {
        int r  = wm + mt*16 + (lane & 15);
        int kc = lane >> 4;
        offA[mt] = r*32 + ((kc ^ ((r>>2)&1)) << 4);
    }
    #pragma unroll
    for (int nt = 0; nt < 4; nt++) {
        int il = lane & 15;
        int r  = wn + nt*8 + (il & 7);
        int kc = (il >> 3) & 1;
        offB[nt] = r*32 + ((kc ^ ((r>>2)&1)) << 4);
    }

    float acc[4][4][4];
    #pragma unroll
    for (int mt = 0; mt < 4; mt++)
        #pragma unroll
        for (int nt = 0; nt < 4; nt++)
            #pragma unroll
            for (int e = 0; e < 4; e++) acc[mt][nt][e] = 0.0f;

    #pragma unroll
    for (int t = 0; t < 4; t++)
        CPASYNC16(smbase + t*4096 + dsto, srcp[t]);
    asm volatile("cp.async.commit_group;" ::: "memory");

    for (int c = 0; c < NCHUNK; c++) {
        if (c + 1 < NCHUNK) {
            const uint32_t db = smbase + ((c+1)&1)*16384;
            #pragma unroll
            for (int t = 0; t < 4; t++)
                CPASYNC16(db + t*4096 + dsto, srcp[t] + (c+1)*CHUNK);
            asm volatile("cp.async.commit_group;" ::: "memory");
            asm volatile("cp.async.wait_group 1;" ::: "memory");
        } else {
            asm volatile("cp.async.wait_group 0;" ::: "memory");
        }
        __syncthreads();

        const uint32_t sb  = smbase + (c&1)*16384;
        const uint32_t aAh = sb, aAl = sb + 4096, aBh = sb + 8192, aBl = sb + 12288;

        uint32_t af[4][4], bh[4][2], bl[4][2];
        #pragma unroll
        for (int mt = 0; mt < 4; mt++) LDSM4(af[mt], aAh + offA[mt]);
        #pragma unroll
        for (int nt = 0; nt < 4; nt++) LDSM2(bh[nt], aBh + offB[nt]);
        #pragma unroll
        for (int mt = 0; mt < 4; mt++)
            #pragma unroll
            for (int nt = 0; nt < 4; nt++) MMA16816(acc[mt][nt], af[mt], bh[nt]);

        #pragma unroll
        for (int nt = 0; nt < 4; nt++) LDSM2(bl[nt], aBl + offB[nt]);
        #pragma unroll
        for (int mt = 0; mt < 4; mt++)
            #pragma unroll
            for (int nt = 0; nt < 4; nt++) MMA16816(acc[mt][nt], af[mt], bl[nt]);

        #pragma unroll
        for (int mt = 0; mt < 4; mt++) LDSM4(af[mt], aAl + offA[mt]);
        #pragma unroll
        for (int mt = 0; mt < 4; mt++)
            #pragma unroll
            for (int nt = 0; nt < 4; nt++) MMA16816(acc[mt][nt], af[mt], bh[nt]);

        __syncthreads();
    }

    const int group = lane >> 2, lane4 = lane & 3;
    #pragma unroll
    for (int mt = 0; mt < 4; mt++) {
        #pragma unroll
        for (int nt = 0; nt < 4; nt++) {
            int m = m0 + wm + mt*16 + group;
            int n = n0 + wn + nt*8 + lane4*2;
            float b0 = 0.f, b1 = 0.f;
            if (which) { b0 = bias[n]; b1 = bias[n+1]; }
            float2 v0, v1;
            v0.x = acc[mt][nt][0] + b0; v0.y = acc[mt][nt][1] + b1;
            v1.x = acc[mt][nt][2] + b0; v1.y = acc[mt][nt][3] + b1;
            *(float2*)&out[(size_t)m*nld + n]     = v0;
            *(float2*)&out[(size_t)(m+8)*nld + n] = v1;
        }
    }
}

// ---------------------------------------------------------------------------
// Tensor-core flash attention. Grid (CS/128, CH, CB), 256 thr, 64KB dyn smem.
// 8 warps x 16 q-rows. K/Vt bf16-split tiles (64 kv) double-buffered.
// Tile geometry: [64 rows][128B], 16B chunks XOR-swizzled chunk^(row&7).
// ---------------------------------------------------------------------------
#define ATILE  8192
#define ASTAGE 32768
#define ATTN_SMEM (2*ASTAGE)

__global__ __launch_bounds__(256, 1) void attn_mma()
{
    extern __shared__ uint8_t smA[];
    const int tid = threadIdx.x, warp = tid >> 5, lane = tid & 31;
    const int bq = blockIdx.z;                       // batch
    const int h  = blockIdx.y;
    const size_t bh = (size_t)bq*CH + h;
    const int q0 = blockIdx.x * 128;
    const uint32_t sb = s2u(smA);

    // ---- Q fragments (A operand), hi/lo, 4 k16-chunks, resident in regs ----
    const int g = lane >> 2, tq = (lane & 3) * 2;
    uint32_t qh[4][4], ql[4][4];
    {
        const __nv_bfloat16* qb = g_qsh + (bh*CS + q0 + warp*16)*CHD;
        const __nv_bfloat16* lb = g_qsl + (bh*CS + q0 + warp*16)*CHD;
        #pragma unroll
        for (int kk = 0; kk < 4; kk++) {
            qh[kk][0] = *(const uint32_t*)(qb + (size_t)g*CHD     + kk*16 + tq);
            qh[kk][1] = *(const uint32_t*)(qb + (size_t)(g+8)*CHD + kk*16 + tq);
            qh[kk][2] = *(const uint32_t*)(qb + (size_t)g*CHD     + kk*16 + 8 + tq);
            qh[kk][3] = *(const uint32_t*)(qb + (size_t)(g+8)*CHD + kk*16 + 8 + tq);
            ql[kk][0] = *(const uint32_t*)(lb + (size_t)g*CHD     + kk*16 + tq);
            ql[kk][1] = *(const uint32_t*)(lb + (size_t)(g+8)*CHD + kk*16 + tq);
            ql[kk][2] = *(const uint32_t*)(lb + (size_t)g*CHD     + kk*16 + 8 + tq);
            ql[kk][3] = *(const uint32_t*)(lb + (size_t)(g+8)*CHD + kk*16 + 8 + tq);
        }
    }

    // ---- loader setup: thread -> (row = tid>>3 in 0..31, chunk = tid&7) ----
    const int lrow = tid >> 3, lch = tid & 7;
    const uint32_t doff = lrow*128 + ((lch ^ (lrow & 7)) << 4);   // +4096 for row+32
    const __nv_bfloat16* pKh = g_kh2 + (bh*CS + lrow)*CHD + lch*8;
    const __nv_bfloat16* pKl = g_kl2 + (bh*CS + lrow)*CHD + lch*8;
    const __nv_bfloat16* pVh = g_vth + (bh*CHD + lrow)*CS + lch*8;
    const __nv_bfloat16* pVl = g_vtl + (bh*CHD + lrow)*CS + lch*8;

    // ---- ldmatrix lane addressing (B operand), swizzle-folded ----
    const int r8 = lane & 7, cs4 = lane >> 3;                      // cs4: 0..3
    const uint32_t loK = r8*128 + ((cs4 ^ r8) << 4);               // ^ (kk2<<6) selects k16 pair

    // ---- state ----
    float O[8][4];
    #pragma unroll
    for (int dt = 0; dt < 8; dt++)
        #pragma unroll
        for (int e = 0; e < 4; e++) O[dt][e] = 0.0f;
    float m0r = -1e30f, m1r = -1e30f, l0r = 0.0f, l1r = 0.0f;

    // ---- prologue: load chunk 0 ----
    {
        CPASYNC16(sb + doff,          pKh); CPASYNC16(sb + doff + 4096,          pKh + 32*CHD);
        CPASYNC16(sb + ATILE + doff,  pKl); CPASYNC16(sb + ATILE + doff + 4096,  pKl + 32*CHD);
        CPASYNC16(sb + 2*ATILE + doff,pVh); CPASYNC16(sb + 2*ATILE + doff + 4096,pVh + 32*CS);
        CPASYNC16(sb + 3*ATILE + doff,pVl); CPASYNC16(sb + 3*ATILE + doff + 4096,pVl + 32*CS);
        asm volatile("cp.async.commit_group;" ::: "memory");
        pKh += 64*CHD; pKl += 64*CHD; pVh += 64; pVl += 64;
    }

    for (int c = 0; c < CS/64; c++) {
        if (c + 1 < CS/64) {
            const uint32_t db = sb + ((c+1)&1)*ASTAGE;
            CPASYNC16(db + doff,          pKh); CPASYNC16(db + doff + 4096,          pKh + 32*CHD);
            CPASYNC16(db + ATILE + doff,  pKl); CPASYNC16(db + ATILE + doff + 4096,  pKl + 32*CHD);
            CPASYNC16(db + 2*ATILE + doff,pVh); CPASYNC16(db + 2*ATILE + doff + 4096,pVh + 32*CS);
            CPASYNC16(db + 3*ATILE + doff,pVl); CPASYNC16(db + 3*ATILE + doff + 4096,pVl + 32*CS);
            asm volatile("cp.async.commit_group;" ::: "memory");
            asm volatile("cp.async.wait_group 1;" ::: "memory");
            pKh += 64*CHD; pKl += 64*CHD; pVh += 64; pVl += 64;
        } else {
            asm volatile("cp.async.wait_group 0;" ::: "memory");
        }
        __syncthreads();

        const uint32_t bufb = sb + (c&1)*ASTAGE;
        const uint32_t aKh = bufb, aKl = bufb + ATILE;
        const uint32_t aVh = bufb + 2*ATILE, aVl = bufb + 3*ATILE;

        // ---- S = Q' K^T (3-term split), accumulators sA[nt][4] ----
        float sA[8][4];
        #pragma unroll
        for (int nt = 0; nt < 8; nt++)
            #pragma unroll
            for (int e = 0; e < 4; e++) sA[nt][e] = 0.0f;

        #pragma unroll
        for (int kk2 = 0; kk2 < 2; kk2++) {
            const uint32_t xo = loK ^ (kk2 << 6);
            #pragma unroll
            for (int nt = 0; nt < 8; nt++) {
                uint32_t bh4[4], bl4[4];
                LDSM4(bh4, aKh + nt*1024 + xo);
                LDSM4(bl4, aKl + nt*1024 + xo);
                MMA16816(sA[nt], qh[2*kk2],   bh4);
                MMA16816(sA[nt], ql[2*kk2],   bh4);
                MMA16816(sA[nt], qh[2*kk2],   bl4);
                MMA16816(sA[nt], qh[2*kk2+1], bh4+2);
                MMA16816(sA[nt], ql[2*kk2+1], bh4+2);
                MMA16816(sA[nt], qh[2*kk2+1], bl4+2);
            }
        }

        // ---- online softmax (base-2), rows g and g+8 ----
        {
            float mx0 = sA[0][0], mx1 = sA[0][2];
            #pragma unroll
            for (int nt = 0; nt < 8; nt++) {
                mx0 = fmaxf(mx0, fmaxf(sA[nt][0], sA[nt][1]));
                mx1 = fmaxf(mx1, fmaxf(sA[nt][2], sA[nt][3]));
            }
            mx0 = fmaxf(mx0, __shfl_xor_sync(0xffffffffu, mx0, 1));
            mx0 = fmaxf(mx0, __shfl_xor_sync(0xffffffffu, mx0, 2));
            mx1 = fmaxf(mx1, __shfl_xor_sync(0xffffffffu, mx1, 1));
            mx1 = fmaxf(mx1, __shfl_xor_sync(0xffffffffu, mx1, 2));
            float mn0 = fmaxf(m0r, mx0), mn1 = fmaxf(m1r, mx1);
            float sc0 = ex2f(fmaxf(m0r - mn0, -126.f));
            float sc1 = ex2f(fmaxf(m1r - mn1, -126.f));
            m0r = mn0; m1r = mn1;
            float s0 = 0.f, s1 = 0.f;
            #pragma unroll
            for (int nt = 0; nt < 8; nt++) {
                sA[nt][0] = ex2f(sA[nt][0] - mn0);
                sA[nt][1] = ex2f(sA[nt][1] - mn0);
                sA[nt][2] = ex2f(sA[nt][2] - mn1);
                sA[nt][3] = ex2f(sA[nt][3] - mn1);
                s0 += sA[nt][0] + sA[nt][1];
                s1 += sA[nt][2] + sA[nt][3];
            }
            s0 += __shfl_xor_sync(0xffffffffu, s0, 1);
            s0 += __shfl_xor_sync(0xffffffffu, s0, 2);
            s1 += __shfl_xor_sync(0xffffffffu, s1, 1);
            s1 += __shfl_xor_sync(0xffffffffu, s1, 2);
            l0r = l0r*sc0 + s0; l1r = l1r*sc1 + s1;
            #pragma unroll
            for (int dt = 0; dt < 8; dt++) {
                O[dt][0] *= sc0; O[dt][1] *= sc0;
                O[dt][2] *= sc1; O[dt][3] *= sc1;
            }
        }

        // ---- O += P V (3-term split); P frags built from sA in-place ----
        #pragma unroll
        for (int j2 = 0; j2 < 2; j2++) {
            uint32_t phA[4], plA[4], phB[4], plB[4];
            #pragma unroll
            for (int jj = 0; jj < 2; jj++) {
                const int j = 2*j2 + jj;
                uint32_t* PH = jj ? phB : phA;
                uint32_t* PL = jj ? plB : plA;
                #pragma unroll
                for (int half = 0; half < 2; half++) {       // nt = 2j + half
                    const int nt = 2*j + half;
                    __nv_bfloat16 h0 = __float2bfloat16(sA[nt][0]);
                    __nv_bfloat16 h1 = __float2bfloat16(sA[nt][1]);
                    __nv_bfloat16 h2 = __float2bfloat16(sA[nt][2]);
                    __nv_bfloat16 h3 = __float2bfloat16(sA[nt][3]);
                    __nv_bfloat16 e0 = __float2bfloat16(sA[nt][0] - __bfloat162float(h0));
                    __nv_bfloat16 e1 = __float2bfloat16(sA[nt][1] - __bfloat162float(h1));
                    __nv_bfloat16 e2 = __float2bfloat16(sA[nt][2] - __bfloat162float(h2));
                    __nv_bfloat16 e3 = __float2bfloat16(sA[nt][3] - __bfloat162float(h3));
                    PH[2*half]   = pack_bf2(h0, h1);   // (row g,   k pair)
                    PH[2*half+1] = pack_bf2(h2, h3);   // (row g+8, k pair)
                    PL[2*half]   = pack_bf2(e0, e1);
                    PL[2*half+1] = pack_bf2(e2, e3);
                }
            }
            const uint32_t xo = loK ^ (j2 << 6);
            #pragma unroll
            for (int dt = 0; dt < 8; dt++) {
                uint32_t vh4[4], vl4[4];
                LDSM4(vh4, aVh + dt*1024 + xo);
                LDSM4(vl4, aVl + dt*1024 + xo);
                MMA16816(O[dt], phA, vh4);
                MMA16816(O[dt], plA, vh4);
                MMA16816(O[dt], phA, vl4);
                MMA16816(O[dt], phB, vh4+2);
                MMA16816(O[dt], plB, vh4+2);
                MMA16816(O[dt], phB, vl4+2);
            }
        }

        __syncthreads();
    }

    // ---- epilogue: normalize, split hi/lo, write g_ah/g_al directly ----
    const float inv0 = 1.0f / l0r, inv1 = 1.0f / l1r;
    const size_t row0 = ((size_t)bq*CS + q0 + warp*16 + g) * CD + h*CHD;
    const size_t row8 = row0 + 8*CD;
    #pragma unroll
    for (int dt = 0; dt < 8; dt++) {
        const int d = dt*8 + tq;
        float o0 = O[dt][0]*inv0, o1 = O[dt][1]*inv0;
        float o2 = O[dt][2]*inv1, o3 = O[dt][3]*inv1;
        __nv_bfloat16 h0 = __float2bfloat16(o0), h1 = __float2bfloat16(o1);
        __nv_bfloat16 h2 = __float2bfloat16(o2), h3 = __float2bfloat16(o3);
        __nv_bfloat16 e0 = __float2bfloat16(o0 - __bfloat162float(h0));
        __nv_bfloat16 e1 = __float2bfloat16(o1 - __bfloat162float(h1));
        __nv_bfloat16 e2 = __float2bfloat16(o2 - __bfloat162float(h2));
        __nv_bfloat16 e3 = __float2bfloat16(o3 - __bfloat162float(h3));
        *(uint32_t*)(g_ah + row0 + d) = pack_bf2(h0, h1);
        *(uint32_t*)(g_al + row0 + d) = pack_bf2(e0, e1);
        *(uint32_t*)(g_ah + row8 + d) = pack_bf2(h2, h3);
        *(uint32_t*)(g_al + row8 + d) = pack_bf2(e2, e3);
    }
}

// ---------------------------------------------------------------------------

extern "C" void kernel_launch(void* const* d_in, const int* in_sizes, int n_in,
                              void* d_out, int out_size)
{
    const float* latents = (const float*)d_in[0];   // [2,2048,1024]
    const float* w_qkv   = (const float*)d_in[1];   // [3072,1024]
    const float* w_out   = (const float*)d_in[2];   // [1024,1024]
    const float* b_out   = (const float*)d_in[3];   // [1024]
    float* out = (float*)d_out;
    (void)in_sizes; (void)n_in; (void)out_size;

    cudaFuncSetAttribute(attn_mma, cudaFuncAttributeMaxDynamicSharedMemorySize, ATTN_SMEM);

    // hi/lo splits of GEMM operands
    conv_x <<<CM*CD/4/256,   256>>>((const float4*)latents);
    conv_wq<<<NQKV*CD/4/256, 256>>>((const float4*)w_qkv);
    conv_wo<<<CD*CD/4/256,   256>>>((const float4*)w_out);

    // QKV projection -> g_qkv [4096, 3072]
    mm_bf16<<<dim3(NQKV/128, CM/128), 256>>>(0, nullptr, nullptr);

    // split Q/K/V into bf16 hi/lo attention operands (V transposed)
    conv_qkv<<<dim3(CS/64, CH, CB), 256>>>();

    // tensor-core flash attention -> g_ah/g_al (bf16 hi/lo, out-proj ready)
    attn_mma<<<dim3(CS/128, CH, CB), 256, ATTN_SMEM>>>();

    // out-proj + bias -> d_out
    mm_bf16<<<dim3(CD/128, CM/128), 256>>>(1, out, b_out);
}

// round 8
// speedup vs baseline: 2.9536x; 1.0658x over previous
#include <cuda_runtime.h>
#include <cuda_bf16.h>
#include <cstdint>

// Problem constants
#define CB 2
#define CS 2048
#define CD 1024
#define CH 16
#define CHD 64
#define CM 4096          // B*S rows
#define NQKV 3072
#define CHUNK 16
#define NCHUNK (CD/CHUNK)   // 64

// ---------------------------------------------------------------------------
// Device-global scratch (allocation-free rule)
// ---------------------------------------------------------------------------
__device__ __nv_bfloat16 g_xh[(size_t)CM*CD],  g_xl[(size_t)CM*CD];      // latents hi/lo
__device__ __nv_bfloat16 g_wqh[(size_t)NQKV*CD], g_wql[(size_t)NQKV*CD]; // w_qkv hi/lo
__device__ __nv_bfloat16 g_woh[(size_t)CD*CD], g_wol[(size_t)CD*CD];     // w_out hi/lo
__device__ __nv_bfloat16 g_ah[(size_t)CM*CD],  g_al[(size_t)CM*CD];      // attn out hi/lo
__device__ float g_qkv[(size_t)CM*NQKV];   // row-major [4096, 3072]
// attention operands (bf16 hi/lo): Q scaled by 0.125*log2e
__device__ __nv_bfloat16 g_qsh[(size_t)CB*CH*CS*CHD], g_qsl[(size_t)CB*CH*CS*CHD]; // [bh,s,d]
__device__ __nv_bfloat16 g_kh2[(size_t)CB*CH*CS*CHD], g_kl2[(size_t)CB*CH*CS*CHD]; // [bh,s,d]
__device__ __nv_bfloat16 g_vth[(size_t)CB*CH*CHD*CS], g_vtl[(size_t)CB*CH*CHD*CS]; // [bh,d,s]

// ---------------------------------------------------------------------------
// PTX helpers (arch-agnostic: ldmatrix + mma.sync, sm_80+)
// ---------------------------------------------------------------------------
static __device__ __forceinline__ uint32_t s2u(const void* p){
    uint32_t a;
    asm("{ .reg .u64 t; cvta.to.shared.u64 t, %1; cvt.u32.u64 %0, t; }" : "=r"(a) : "l"(p));
    return a;
}
static __device__ __forceinline__ float ex2f(float x){
    float r; asm("ex2.approx.f32 %0, %1;" : "=f"(r) : "f"(x)); return r;
}
#define LDSM4(r, addr) \
    asm volatile("ldmatrix.sync.aligned.m8n8.x4.shared.b16 {%0,%1,%2,%3}, [%4];" \
        : "=r"((r)[0]), "=r"((r)[1]), "=r"((r)[2]), "=r"((r)[3]) : "r"(addr))
#define LDSM2(r, addr) \
    asm volatile("ldmatrix.sync.aligned.m8n8.x2.shared.b16 {%0,%1}, [%2];" \
        : "=r"((r)[0]), "=r"((r)[1]) : "r"(addr))
// NOTE: non-volatile — register-only semantics, lets ptxas interleave chains.
#define MMA16816(d, a, b) \
    asm("mma.sync.aligned.m16n8k16.row.col.f32.bf16.bf16.f32 " \
        "{%0,%1,%2,%3}, {%4,%5,%6,%7}, {%8,%9}, {%0,%1,%2,%3};" \
        : "+f"((d)[0]), "+f"((d)[1]), "+f"((d)[2]), "+f"((d)[3]) \
        : "r"((a)[0]), "r"((a)[1]), "r"((a)[2]), "r"((a)[3]), "r"((b)[0]), "r"((b)[1]))
#define CPASYNC16(dst, src) \
    asm volatile("cp.async.cg.shared.global [%0], [%1], 16;" :: "r"(dst), "l"(src) : "memory")

static __device__ __forceinline__ uint32_t pack_bf2(__nv_bfloat16 a, __nv_bfloat16 b){
    __nv_bfloat162 t = __halves2bfloat162(a, b);   // low = a, high = b
    return *reinterpret_cast<uint32_t*>(&t);
}

// ---------------------------------------------------------------------------
// fp32 -> bf16 hi/lo split conversion (for GEMM operands)
// ---------------------------------------------------------------------------
static __device__ __forceinline__ void conv_body(const float4* __restrict__ src,
    __nv_bfloat16* __restrict__ hi, __nv_bfloat16* __restrict__ lo, int n4)
{
    int i = blockIdx.x * 256 + threadIdx.x;
    if (i >= n4) return;
    float4 v = src[i];
    __nv_bfloat162 h01 = __floats2bfloat162_rn(v.x, v.y);
    __nv_bfloat162 h23 = __floats2bfloat162_rn(v.z, v.w);
    __nv_bfloat162 l01 = __floats2bfloat162_rn(v.x - __low2float(h01), v.y - __high2float(h01));
    __nv_bfloat162 l23 = __floats2bfloat162_rn(v.z - __low2float(h23), v.w - __high2float(h23));
    uint2 H, L;
    H.x = *reinterpret_cast<unsigned*>(&h01); H.y = *reinterpret_cast<unsigned*>(&h23);
    L.x = *reinterpret_cast<unsigned*>(&l01); L.y = *reinterpret_cast<unsigned*>(&l23);
    *reinterpret_cast<uint2*>(hi + (size_t)i*4) = H;
    *reinterpret_cast<uint2*>(lo + (size_t)i*4) = L;
}
__global__ __launch_bounds__(256) void conv_x (const float4* s){ conv_body(s, g_xh,  g_xl,  CM*CD/4); }
__global__ __launch_bounds__(256) void conv_wq(const float4* s){ conv_body(s, g_wqh, g_wql, NQKV*CD/4); }
__global__ __launch_bounds__(256) void conv_wo(const float4* s){ conv_body(s, g_woh, g_wol, CD*CD/4); }

// ---------------------------------------------------------------------------
// Split g_qkv -> attention operands. Grid (CS/64, CH, CB), 256 thr.
// Q scaled by 0.125*log2e (base-2 softmax). V transposed to [bh,d,s] via smem.
// ---------------------------------------------------------------------------
__global__ __launch_bounds__(256) void conv_qkv()
{
    __shared__ float vs[64][65];
    const int tid = threadIdx.x;
    const int kt = blockIdx.x, h = blockIdx.y, b = blockIdx.z;
    const size_t bh = (size_t)b*CH + h;
    const float* base = g_qkv + ((size_t)(b*CS + kt*64))*NQKV + h*192;
    const float QSC = 0.125f * 1.44269504f;

    for (int i = tid; i < 64*16; i += 256) {
        int s = i >> 4, d4 = i & 15;
        const float* p = base + (size_t)s*NQKV + d4*4;
        size_t o = (bh*CS + kt*64 + s)*CHD + d4*4;
        float4 q = *(const float4*)p;
        q.x *= QSC; q.y *= QSC; q.z *= QSC; q.w *= QSC;
        {
            __nv_bfloat162 h01 = __floats2bfloat162_rn(q.x, q.y);
            __nv_bfloat162 h23 = __floats2bfloat162_rn(q.z, q.w);
            __nv_bfloat162 l01 = __floats2bfloat162_rn(q.x - __low2float(h01), q.y - __high2float(h01));
            __nv_bfloat162 l23 = __floats2bfloat162_rn(q.z - __low2float(h23), q.w - __high2float(h23));
            uint2 H = { *(unsigned*)&h01, *(unsigned*)&h23 };
            uint2 L = { *(unsigned*)&l01, *(unsigned*)&l23 };
            *reinterpret_cast<uint2*>(g_qsh + o) = H;
            *reinterpret_cast<uint2*>(g_qsl + o) = L;
        }
        float4 k = *(const float4*)(p + 64);
        {
            __nv_bfloat162 h01 = __floats2bfloat162_rn(k.x, k.y);
            __nv_bfloat162 h23 = __floats2bfloat162_rn(k.z, k.w);
            __nv_bfloat162 l01 = __floats2bfloat162_rn(k.x - __low2float(h01), k.y - __high2float(h01));
            __nv_bfloat162 l23 = __floats2bfloat162_rn(k.z - __low2float(h23), k.w - __high2float(h23));
            uint2 H = { *(unsigned*)&h01, *(unsigned*)&h23 };
            uint2 L = { *(unsigned*)&l01, *(unsigned*)&l23 };
            *reinterpret_cast<uint2*>(g_kh2 + o) = H;
            *reinterpret_cast<uint2*>(g_kl2 + o) = L;
        }
        float4 v = *(const float4*)(p + 128);
        vs[s][d4*4+0] = v.x; vs[s][d4*4+1] = v.y; vs[s][d4*4+2] = v.z; vs[s][d4*4+3] = v.w;
    }
    __syncthreads();
    for (int i = tid; i < 64*16; i += 256) {
        int d = i >> 4, s4 = i & 15;
        float x0 = vs[s4*4+0][d], x1 = vs[s4*4+1][d], x2 = vs[s4*4+2][d], x3 = vs[s4*4+3][d];
        __nv_bfloat16 h0 = __float2bfloat16(x0), h1 = __float2bfloat16(x1);
        __nv_bfloat16 h2 = __float2bfloat16(x2), h3 = __float2bfloat16(x3);
        __nv_bfloat16 l0 = __float2bfloat16(x0 - __bfloat162float(h0));
        __nv_bfloat16 l1 = __float2bfloat16(x1 - __bfloat162float(h1));
        __nv_bfloat16 l2 = __float2bfloat16(x2 - __bfloat162float(h2));
        __nv_bfloat16 l3 = __float2bfloat16(x3 - __bfloat162float(h3));
        size_t o = (bh*CHD + d)*CS + kt*64 + s4*4;
        uint2 H = { pack_bf2(h0,h1), pack_bf2(h2,h3) };
        uint2 L = { pack_bf2(l0,l1), pack_bf2(l2,l3) };
        *reinterpret_cast<uint2*>(g_vth + o) = H;
        *reinterpret_cast<uint2*>(g_vtl + o) = L;
    }
}

// ---------------------------------------------------------------------------
// mma.sync bf16-split GEMM: out = A @ B^T. CTA 128x128, K-chunk 16.
// 4-stage cp.async pipeline, ONE __syncthreads per chunk:
//   iter c: wait_group 2 (chunk c resident) -> sync (all readers of the
//   stage about to be overwritten are done) -> issue chunk c+3 -> compute c.
// 64KB dynamic smem, 2 CTAs/SM.
// ---------------------------------------------------------------------------
#define MMSTAGE 16384
#define MM_SMEM (4*MMSTAGE)

__global__ __launch_bounds__(256, 2) void mm_bf16(int which, float* __restrict__ outp,
                                                  const float* __restrict__ bias)
{
    extern __shared__ uint8_t smm[];
    const int tid  = threadIdx.x;
    const int m0   = blockIdx.y * 128;
    const int n0   = blockIdx.x * 128;

    const __nv_bfloat16 *Ah, *Al, *Bh, *Bl;
    float* out; int nld;
    if (which == 0) { Ah=g_xh; Al=g_xl; Bh=g_wqh; Bl=g_wql; out=g_qkv; nld=NQKV; }
    else            { Ah=g_ah; Al=g_al; Bh=g_woh; Bl=g_wol; out=outp;  nld=CD;   }

    const int lrow = tid >> 1;
    const int lkc  = tid & 1;
    const uint32_t smbase = s2u(smm);
    const uint32_t dsto   = lrow*32 + ((lkc ^ ((lrow>>2)&1)) << 4);
    const __nv_bfloat16* srcp[4] = {
        Ah + (size_t)(m0+lrow)*CD + lkc*8,
        Al + (size_t)(m0+lrow)*CD + lkc*8,
        Bh + (size_t)(n0+lrow)*CD + lkc*8,
        Bl + (size_t)(n0+lrow)*CD + lkc*8 };

    const int warp = tid >> 5, lane = tid & 31;
    const int wm = (warp >> 2) * 64;
    const int wn = (warp & 3) * 32;
    uint32_t offA[4], offB[4];
    #pragma unroll
    for (int mt = 0; mt < 4; mt++) {
        int r  = wm + mt*16 + (lane & 15);
        int kc = lane >> 4;
        offA[mt] = r*32 + ((kc ^ ((r>>2)&1)) << 4);
    }
    #pragma unroll
    for (int nt = 0; nt < 4; nt++) {
        int il = lane & 15;
        int r  = wn + nt*8 + (il & 7);
        int kc = (il >> 3) & 1;
        offB[nt] = r*32 + ((kc ^ ((r>>2)&1)) << 4);
    }

    float acc[4][4][4];
    #pragma unroll
    for (int mt = 0; mt < 4; mt++)
        #pragma unroll
        for (int nt = 0; nt < 4; nt++)
            #pragma unroll
            for (int e = 0; e < 4; e++) acc[mt][nt][e] = 0.0f;

    // ---- prologue: stages 0..2 ----
    #pragma unroll
    for (int s = 0; s < 3; s++) {
        const uint32_t db = smbase + s*MMSTAGE;
        #pragma unroll
        for (int t = 0; t < 4; t++)
            CPASYNC16(db + t*4096 + dsto, srcp[t] + s*CHUNK);
        asm volatile("cp.async.commit_group;" ::: "memory");
    }

    for (int c = 0; c < NCHUNK; c++) {
        asm volatile("cp.async.wait_group 2;" ::: "memory");
        __syncthreads();
        if (c + 3 < NCHUNK) {
            const uint32_t db = smbase + ((c+3)&3)*MMSTAGE;
            #pragma unroll
            for (int t = 0; t < 4; t++)
                CPASYNC16(db + t*4096 + dsto, srcp[t] + (c+3)*CHUNK);
        }
        asm volatile("cp.async.commit_group;" ::: "memory");

        const uint32_t sb  = smbase + (c&3)*MMSTAGE;
        const uint32_t aAh = sb, aAl = sb + 4096, aBh = sb + 8192, aBl = sb + 12288;

        uint32_t af[4][4], bh[4][2], bl[4][2];
        #pragma unroll
        for (int mt = 0; mt < 4; mt++) LDSM4(af[mt], aAh + offA[mt]);
        #pragma unroll
        for (int nt = 0; nt < 4; nt++) LDSM2(bh[nt], aBh + offB[nt]);
        #pragma unroll
        for (int mt = 0; mt < 4; mt++)
            #pragma unroll
            for (int nt = 0; nt < 4; nt++) MMA16816(acc[mt][nt], af[mt], bh[nt]);

        #pragma unroll
        for (int nt = 0; nt < 4; nt++) LDSM2(bl[nt], aBl + offB[nt]);
        #pragma unroll
        for (int mt = 0; mt < 4; mt++)
            #pragma unroll
            for (int nt = 0; nt < 4; nt++) MMA16816(acc[mt][nt], af[mt], bl[nt]);

        #pragma unroll
        for (int mt = 0; mt < 4; mt++) LDSM4(af[mt], aAl + offA[mt]);
        #pragma unroll
        for (int mt = 0; mt < 4; mt++)
            #pragma unroll
            for (int nt = 0; nt < 4; nt++) MMA16816(acc[mt][nt], af[mt], bh[nt]);
    }

    const int group = lane >> 2, lane4 = lane & 3;
    #pragma unroll
    for (int mt = 0; mt < 4; mt++) {
        #pragma unroll
        for (int nt = 0; nt < 4; nt++) {
            int m = m0 + wm + mt*16 + group;
            int n = n0 + wn + nt*8 + lane4*2;
            float b0 = 0.f, b1 = 0.f;
            if (which) { b0 = bias[n]; b1 = bias[n+1]; }
            float2 v0, v1;
            v0.x = acc[mt][nt][0] + b0; v0.y = acc[mt][nt][1] + b1;
            v1.x = acc[mt][nt][2] + b0; v1.y = acc[mt][nt][3] + b1;
            *(float2*)&out[(size_t)m*nld + n]     = v0;
            *(float2*)&out[(size_t)(m+8)*nld + n] = v1;
        }
    }
}

// ---------------------------------------------------------------------------
// Tensor-core flash attention. Grid (CS/128, CH, CB), 256 thr, 96KB dyn smem.
// 8 warps x 16 q-rows. K/Vt bf16-split tiles (64 kv), 3-stage pipeline,
// ONE __syncthreads per chunk (same hazard argument as mm_bf16).
// ---------------------------------------------------------------------------
#define ATILE  8192
#define ASTAGE 32768
#define ATTN_SMEM (3*ASTAGE)

__global__ __launch_bounds__(256, 1) void attn_mma()
{
    extern __shared__ uint8_t smA[];
    const int tid = threadIdx.x, warp = tid >> 5, lane = tid & 31;
    const int bq = blockIdx.z;
    const int h  = blockIdx.y;
    const size_t bh = (size_t)bq*CH + h;
    const int q0 = blockIdx.x * 128;
    const uint32_t sb = s2u(smA);

    // ---- Q fragments (A operand), hi/lo, 4 k16-chunks, resident in regs ----
    const int g = lane >> 2, tq = (lane & 3) * 2;
    uint32_t qh[4][4], ql[4][4];
    {
        const __nv_bfloat16* qb = g_qsh + (bh*CS + q0 + warp*16)*CHD;
        const __nv_bfloat16* lb = g_qsl + (bh*CS + q0 + warp*16)*CHD;
        #pragma unroll
        for (int kk = 0; kk < 4; kk++) {
            qh[kk][0] = *(const uint32_t*)(qb + (size_t)g*CHD     + kk*16 + tq);
            qh[kk][1] = *(const uint32_t*)(qb + (size_t)(g+8)*CHD + kk*16 + tq);
            qh[kk][2] = *(const uint32_t*)(qb + (size_t)g*CHD     + kk*16 + 8 + tq);
            qh[kk][3] = *(const uint32_t*)(qb + (size_t)(g+8)*CHD + kk*16 + 8 + tq);
            ql[kk][0] = *(const uint32_t*)(lb + (size_t)g*CHD     + kk*16 + tq);
            ql[kk][1] = *(const uint32_t*)(lb + (size_t)(g+8)*CHD + kk*16 + tq);
            ql[kk][2] = *(const uint32_t*)(lb + (size_t)g*CHD     + kk*16 + 8 + tq);
            ql[kk][3] = *(const uint32_t*)(lb + (size_t)(g+8)*CHD + kk*16 + 8 + tq);
        }
    }

    // ---- loader setup ----
    const int lrow = tid >> 3, lch = tid & 7;
    const uint32_t doff = lrow*128 + ((lch ^ (lrow & 7)) << 4);
    const __nv_bfloat16* pKh = g_kh2 + (bh*CS + lrow)*CHD + lch*8;
    const __nv_bfloat16* pKl = g_kl2 + (bh*CS + lrow)*CHD + lch*8;
    const __nv_bfloat16* pVh = g_vth + (bh*CHD + lrow)*CS + lch*8;
    const __nv_bfloat16* pVl = g_vtl + (bh*CHD + lrow)*CS + lch*8;

    // ---- ldmatrix lane addressing (B operand) ----
    const int r8 = lane & 7, cs4 = lane >> 3;
    const uint32_t loK = r8*128 + ((cs4 ^ r8) << 4);

    // ---- state ----
    float O[8][4];
    #pragma unroll
    for (int dt = 0; dt < 8; dt++)
        #pragma unroll
        for (int e = 0; e < 4; e++) O[dt][e] = 0.0f;
    float m0r = -1e30f, m1r = -1e30f, l0r = 0.0f, l1r = 0.0f;

    // chunk loader (cc in kv-tiles of 64)
    auto issue = [&](int cc, uint32_t db){
        const size_t ko = (size_t)cc*64*CHD, vo = (size_t)cc*64;
        CPASYNC16(db + doff,           pKh+ko); CPASYNC16(db + doff + 4096,           pKh+ko + 32*CHD);
        CPASYNC16(db + ATILE + doff,   pKl+ko); CPASYNC16(db + ATILE + doff + 4096,   pKl+ko + 32*CHD);
        CPASYNC16(db + 2*ATILE + doff, pVh+vo); CPASYNC16(db + 2*ATILE + doff + 4096, pVh+vo + 32*CS);
        CPASYNC16(db + 3*ATILE + doff, pVl+vo); CPASYNC16(db + 3*ATILE + doff + 4096, pVl+vo + 32*CS);
    };

    // ---- prologue: chunks 0,1 into stages 0,1 ----
    issue(0, sb);
    asm volatile("cp.async.commit_group;" ::: "memory");
    issue(1, sb + ASTAGE);
    asm volatile("cp.async.commit_group;" ::: "memory");

    for (int c = 0; c < CS/64; c++) {
        asm volatile("cp.async.wait_group 1;" ::: "memory");
        __syncthreads();
        if (c + 2 < CS/64)
            issue(c+2, sb + ((c+2)%3)*ASTAGE);
        asm volatile("cp.async.commit_group;" ::: "memory");

        const uint32_t bufb = sb + (c%3)*ASTAGE;
        const uint32_t aKh = bufb, aKl = bufb + ATILE;
        const uint32_t aVh = bufb + 2*ATILE, aVl = bufb + 3*ATILE;

        // ---- S = Q' K^T (3-term split) ----
        float sA[8][4];
        #pragma unroll
        for (int nt = 0; nt < 8; nt++)
            #pragma unroll
            for (int e = 0; e < 4; e++) sA[nt][e] = 0.0f;

        #pragma unroll
        for (int kk2 = 0; kk2 < 2; kk2++) {
            const uint32_t xo = loK ^ (kk2 << 6);
            #pragma unroll
            for (int nt = 0; nt < 8; nt++) {
                uint32_t bh4[4], bl4[4];
                LDSM4(bh4, aKh + nt*1024 + xo);
                LDSM4(bl4, aKl + nt*1024 + xo);
                MMA16816(sA[nt], qh[2*kk2],   bh4);
                MMA16816(sA[nt], ql[2*kk2],   bh4);
                MMA16816(sA[nt], qh[2*kk2],   bl4);
                MMA16816(sA[nt], qh[2*kk2+1], bh4+2);
                MMA16816(sA[nt], ql[2*kk2+1], bh4+2);
                MMA16816(sA[nt], qh[2*kk2+1], bl4+2);
            }
        }

        // ---- online softmax (base-2), rows g and g+8 ----
        {
            float mx0 = sA[0][0], mx1 = sA[0][2];
            #pragma unroll
            for (int nt = 0; nt < 8; nt++) {
                mx0 = fmaxf(mx0, fmaxf(sA[nt][0], sA[nt][1]));
                mx1 = fmaxf(mx1, fmaxf(sA[nt][2], sA[nt][3]));
            }
            mx0 = fmaxf(mx0, __shfl_xor_sync(0xffffffffu, mx0, 1));
            mx0 = fmaxf(mx0, __shfl_xor_sync(0xffffffffu, mx0, 2));
            mx1 = fmaxf(mx1, __shfl_xor_sync(0xffffffffu, mx1, 1));
            mx1 = fmaxf(mx1, __shfl_xor_sync(0xffffffffu, mx1, 2));
            float mn0 = fmaxf(m0r, mx0), mn1 = fmaxf(m1r, mx1);
            float sc0 = ex2f(fmaxf(m0r - mn0, -126.f));
            float sc1 = ex2f(fmaxf(m1r - mn1, -126.f));
            m0r = mn0; m1r = mn1;
            float s0 = 0.f, s1 = 0.f;
            #pragma unroll
            for (int nt = 0; nt < 8; nt++) {
                sA[nt][0] = ex2f(sA[nt][0] - mn0);
                sA[nt][1] = ex2f(sA[nt][1] - mn0);
                sA[nt][2] = ex2f(sA[nt][2] - mn1);
                sA[nt][3] = ex2f(sA[nt][3] - mn1);
                s0 += sA[nt][0] + sA[nt][1];
                s1 += sA[nt][2] + sA[nt][3];
            }
            s0 += __shfl_xor_sync(0xffffffffu, s0, 1);
            s0 += __shfl_xor_sync(0xffffffffu, s0, 2);
            s1 += __shfl_xor_sync(0xffffffffu, s1, 1);
            s1 += __shfl_xor_sync(0xffffffffu, s1, 2);
            l0r = l0r*sc0 + s0; l1r = l1r*sc1 + s1;
            #pragma unroll
            for (int dt = 0; dt < 8; dt++) {
                O[dt][0] *= sc0; O[dt][1] *= sc0;
                O[dt][2] *= sc1; O[dt][3] *= sc1;
            }
        }

        // ---- O += P V (3-term split) ----
        #pragma unroll
        for (int j2 = 0; j2 < 2; j2++) {
            uint32_t phA[4], plA[4], phB[4], plB[4];
            #pragma unroll
            for (int jj = 0; jj < 2; jj++) {
                const int j = 2*j2 + jj;
                uint32_t* PH = jj ? phB : phA;
                uint32_t* PL = jj ? plB : plA;
                #pragma unroll
                for (int half = 0; half < 2; half++) {
                    const int nt = 2*j + half;
                    __nv_bfloat16 h0 = __float2bfloat16(sA[nt][0]);
                    __nv_bfloat16 h1 = __float2bfloat16(sA[nt][1]);
                    __nv_bfloat16 h2 = __float2bfloat16(sA[nt][2]);
                    __nv_bfloat16 h3 = __float2bfloat16(sA[nt][3]);
                    __nv_bfloat16 e0 = __float2bfloat16(sA[nt][0] - __bfloat162float(h0));
                    __nv_bfloat16 e1 = __float2bfloat16(sA[nt][1] - __bfloat162float(h1));
                    __nv_bfloat16 e2 = __float2bfloat16(sA[nt][2] - __bfloat162float(h2));
                    __nv_bfloat16 e3 = __float2bfloat16(sA[nt][3] - __bfloat162float(h3));
                    PH[2*half]   = pack_bf2(h0, h1);
                    PH[2*half+1] = pack_bf2(h2, h3);
                    PL[2*half]   = pack_bf2(e0, e1);
                    PL[2*half+1] = pack_bf2(e2, e3);
                }
            }
            const uint32_t xo = loK ^ (j2 << 6);
            #pragma unroll
            for (int dt = 0; dt < 8; dt++) {
                uint32_t vh4[4], vl4[4];
                LDSM4(vh4, aVh + dt*1024 + xo);
                LDSM4(vl4, aVl + dt*1024 + xo);
                MMA16816(O[dt], phA, vh4);
                MMA16816(O[dt], plA, vh4);
                MMA16816(O[dt], phA, vl4);
                MMA16816(O[dt], phB, vh4+2);
                MMA16816(O[dt], plB, vh4+2);
                MMA16816(O[dt], phB, vl4+2);
            }
        }
    }

    // ---- epilogue ----
    const float inv0 = 1.0f / l0r, inv1 = 1.0f / l1r;
    const size_t row0 = ((size_t)bq*CS + q0 + warp*16 + g) * CD + h*CHD;
    const size_t row8 = row0 + 8*CD;
    #pragma unroll
    for (int dt = 0; dt < 8; dt++) {
        const int d = dt*8 + tq;
        float o0 = O[dt][0]*inv0, o1 = O[dt][1]*inv0;
        float o2 = O[dt][2]*inv1, o3 = O[dt][3]*inv1;
        __nv_bfloat16 h0 = __float2bfloat16(o0), h1 = __float2bfloat16(o1);
        __nv_bfloat16 h2 = __float2bfloat16(o2), h3 = __float2bfloat16(o3);
        __nv_bfloat16 e0 = __float2bfloat16(o0 - __bfloat162float(h0));
        __nv_bfloat16 e1 = __float2bfloat16(o1 - __bfloat162float(h1));
        __nv_bfloat16 e2 = __float2bfloat16(o2 - __bfloat162float(h2));
        __nv_bfloat16 e3 = __float2bfloat16(o3 - __bfloat162float(h3));
        *(uint32_t*)(g_ah + row0 + d) = pack_bf2(h0, h1);
        *(uint32_t*)(g_al + row0 + d) = pack_bf2(e0, e1);
        *(uint32_t*)(g_ah + row8 + d) = pack_bf2(h2, h3);
        *(uint32_t*)(g_al + row8 + d) = pack_bf2(e2, e3);
    }
}

// ---------------------------------------------------------------------------

extern "C" void kernel_launch(void* const* d_in, const int* in_sizes, int n_in,
                              void* d_out, int out_size)
{
    const float* latents = (const float*)d_in[0];   // [2,2048,1024]
    const float* w_qkv   = (const float*)d_in[1];   // [3072,1024]
    const float* w_out   = (const float*)d_in[2];   // [1024,1024]
    const float* b_out   = (const float*)d_in[3];   // [1024]
    float* out = (float*)d_out;
    (void)in_sizes; (void)n_in; (void)out_size;

    cudaFuncSetAttribute(mm_bf16,  cudaFuncAttributeMaxDynamicSharedMemorySize, MM_SMEM);
    cudaFuncSetAttribute(attn_mma, cudaFuncAttributeMaxDynamicSharedMemorySize, ATTN_SMEM);

    // hi/lo splits of GEMM operands
    conv_x <<<CM*CD/4/256,   256>>>((const float4*)latents);
    conv_wq<<<NQKV*CD/4/256, 256>>>((const float4*)w_qkv);
    conv_wo<<<CD*CD/4/256,   256>>>((const float4*)w_out);

    // QKV projection -> g_qkv [4096, 3072]
    mm_bf16<<<dim3(NQKV/128, CM/128), 256, MM_SMEM>>>(0, nullptr, nullptr);

    // split Q/K/V into bf16 hi/lo attention operands (V transposed)
    conv_qkv<<<dim3(CS/64, CH, CB), 256>>>();

    // tensor-core flash attention -> g_ah/g_al (bf16 hi/lo, out-proj ready)
    attn_mma<<<dim3(CS/128, CH, CB), 256, ATTN_SMEM>>>();

    // out-proj + bias -> d_out
    mm_bf16<<<dim3(CD/128, CM/128), 256, MM_SMEM>>>(1, out, b_out);
}